// round 5
// baseline (speedup 1.0000x reference)
#include <cuda_runtime.h>
#include <cstdint>
#include <math.h>

// ---------------------------------------------------------------------------
// NeuralODE Tsit5 — persistent-CTA fp32 kernel, round 4.
// Cost model (validated rounds 1-3): SMEM crossbar charges delivered bytes;
// same-address broadcasts are ~1 wavefront. Therefore:
//   - A operands: LDS.64 same-address broadcasts (row-pairs, swizzled layout)
//   - W operands: LDG via L1/L2 (off the crossbar entirely, no cp.async)
//   - 16x8 register tile per thread, split-K over 4 warp groups
// ---------------------------------------------------------------------------

#define BATCH   4096
#define DIM     64
#define WIDTH   256
#define NTT     101
#define TM      32
#define NCTA    (BATCH / TM)      // 128
#define THREADS 256

// swizzle: element (idx, r) lives at slot r ^ sw(idx), sw multiple of 4
#define SW(idx) ((((idx) >> 3) & 7) << 2)

#define ACT_SIZE (WIDTH * TM)     // 8192 floats = 32KB   layout [256][32]
#define ZK_SIZE  (DIM * TM)       // 2048 floats = 8KB    layout [64][32]
#define RED_SIZE (WIDTH * TM)     // 8192 floats = 32KB

#define SMEM_FLOATS (2*ACT_SIZE + 2*RED_SIZE + ZK_SIZE + ZK_SIZE + 6*ZK_SIZE)
#define SMEM_BYTES  (SMEM_FLOATS * 4)   // 192KB

// Tsit5 tableau
__constant__ float c_A[6][5] = {
    {0.f, 0.f, 0.f, 0.f, 0.f},
    {0.161f, 0.f, 0.f, 0.f, 0.f},
    {-0.008480655492356989f, 0.335480655492357f, 0.f, 0.f, 0.f},
    {2.8971530571054935f, -6.359448489975075f, 4.3622954328695815f, 0.f, 0.f},
    {5.325864828439257f, -11.748883564062828f, 7.4955393428898365f, -0.09249506636175525f, 0.f},
    {5.86145544294642f, -12.92096931784711f, 8.159367898576159f, -0.071584973281401f, -0.028269050394068383f}
};
__constant__ float c_B[6] = {
    0.09646076681806523f, 0.01f, 0.4798896504144996f,
    1.379008574103742f, -3.290069515436081f, 2.324710524099774f
};

// ---- packed f32x2 helpers ----
__device__ __forceinline__ unsigned long long pk2(float lo, float hi) {
    unsigned long long r;
    asm("mov.b64 %0, {%1, %2};" : "=l"(r) : "f"(lo), "f"(hi));
    return r;
}
__device__ __forceinline__ void upk2(unsigned long long v, float &lo, float &hi) {
    asm("mov.b64 {%0, %1}, %2;" : "=f"(lo), "=f"(hi) : "l"(v));
}
__device__ __forceinline__ void ffma2(unsigned long long &d,
                                      unsigned long long a,
                                      unsigned long long b) {
    asm("fma.rn.f32x2 %0, %1, %2, %0;" : "+l"(d) : "l"(a), "l"(b));
}

// ---------------------------------------------------------------------------
// Dense layer:
//   Aout[c][r-swizzled] = act( sum_k W[k][c] * Ain[k][r-swizzled] + b[c] )
// Ain/Aout: SMEM, transposed+swizzled. W,b: global (L1/L2 cached).
// Warp w: rg = w&1 (rows rg*16..+15), ks = w>>2? no: ks = w>>1 (K-slice of 4).
// Lane: CPL columns starting at lane*CPL.
// Split-K reduction: ks2->red0, ks3->red1; sync; ks1 += red0+red1 -> red0;
// sync; ks0 += red0, +bias(in init), tanh, -> Aout; sync.
// ---------------------------------------------------------------------------
template <int K, int N, bool ACT>
__device__ __forceinline__ void layerT(const float *Ain, float *Aout,
                                       const float *__restrict__ Wg,
                                       const float *__restrict__ bg,
                                       float *red0, float *red1) {
    constexpr int CPL = (N == 256) ? 8 : 2;   // cols per lane
    constexpr int KS  = K / 4;                // k-slice length

    const int tid  = threadIdx.x;
    const int w    = tid >> 5;
    const int lane = tid & 31;
    const int rg   = w & 1;
    const int ks   = w >> 1;
    const int r0   = rg * 16;
    const int c0   = lane * CPL;

    unsigned long long acc[8][CPL];
    if (ks == 0) {
#pragma unroll
        for (int c = 0; c < CPL; c++) {
            float b = __ldg(bg + c0 + c);
            unsigned long long bb = pk2(b, b);
#pragma unroll
            for (int rp = 0; rp < 8; rp++) acc[rp][c] = bb;
        }
    } else {
#pragma unroll
        for (int rp = 0; rp < 8; rp++)
#pragma unroll
            for (int c = 0; c < CPL; c++) acc[rp][c] = 0ull;
    }

    // ---- main k-loop: A broadcasts (LDS.64) + W via LDG ----
    const float *Wk = Wg + (size_t)(ks * KS) * N + c0;
#pragma unroll 2
    for (int kk = 0; kk < KS; ++kk) {
        const int k   = ks * KS + kk;
        const int swk = SW(k);
        const float *arow = Ain + k * TM;

        unsigned long long ap[8];
#pragma unroll
        for (int rp = 0; rp < 8; rp++) {
            int r = (r0 + 2 * rp) ^ swk;
            ap[rp] = *reinterpret_cast<const unsigned long long *>(arow + r);
        }

        float wv[CPL];
        if constexpr (CPL == 8) {
            float4 wa = __ldg(reinterpret_cast<const float4 *>(Wk));
            float4 wb = __ldg(reinterpret_cast<const float4 *>(Wk + 4));
            wv[0] = wa.x; wv[1] = wa.y; wv[2] = wa.z; wv[3] = wa.w;
            wv[4] = wb.x; wv[5] = wb.y; wv[6] = wb.z; wv[7] = wb.w;
        } else {
            float2 wa = __ldg(reinterpret_cast<const float2 *>(Wk));
            wv[0] = wa.x; wv[1] = wa.y;
        }
        Wk += N;

#pragma unroll
        for (int c = 0; c < CPL; c++) {
            unsigned long long wp = pk2(wv[c], wv[c]);
#pragma unroll
            for (int rp = 0; rp < 8; rp++) ffma2(acc[rp][c], ap[rp], wp);
        }
    }

    // ---- partial stores: ks 2 -> red0, ks 3 -> red1 ----
    if (ks >= 2) {
        float *dst = (ks == 2) ? red0 : red1;
#pragma unroll
        for (int c = 0; c < CPL; c++) {
            const int cc  = c0 + c;
            const int swc = SW(cc);
            float *base = dst + cc * TM;
#pragma unroll
            for (int q = 0; q < 4; q++) {
                float a0, a1, a2, a3;
                upk2(acc[2 * q][c],     a0, a1);
                upk2(acc[2 * q + 1][c], a2, a3);
                float4 v; v.x = a0; v.y = a1; v.z = a2; v.w = a3;
                *reinterpret_cast<float4 *>(base + ((r0 + 4 * q) ^ swc)) = v;
            }
        }
    }
    __syncthreads();

    // ---- ks1: add red0+red1, store to red0 ----
    if (ks == 1) {
#pragma unroll
        for (int c = 0; c < CPL; c++) {
            const int cc  = c0 + c;
            const int swc = SW(cc);
            const float *b0p = red0 + cc * TM;
            const float *b1p = red1 + cc * TM;
            float *dst = red0 + cc * TM;
#pragma unroll
            for (int q = 0; q < 4; q++) {
                const int off = (r0 + 4 * q) ^ swc;
                float4 v0 = *reinterpret_cast<const float4 *>(b0p + off);
                float4 v1 = *reinterpret_cast<const float4 *>(b1p + off);
                float a0, a1, a2, a3;
                upk2(acc[2 * q][c],     a0, a1);
                upk2(acc[2 * q + 1][c], a2, a3);
                float4 v;
                v.x = a0 + v0.x + v1.x;
                v.y = a1 + v0.y + v1.y;
                v.z = a2 + v0.z + v1.z;
                v.w = a3 + v0.w + v1.w;
                *reinterpret_cast<float4 *>(dst + off) = v;
            }
        }
    }
    __syncthreads();

    // ---- ks0: add red0, tanh, store to Aout ----
    if (ks == 0) {
#pragma unroll
        for (int c = 0; c < CPL; c++) {
            const int cc  = c0 + c;
            const int swc = SW(cc);
            const float *b0p = red0 + cc * TM;
            float *dst = Aout + cc * TM;
#pragma unroll
            for (int q = 0; q < 4; q++) {
                const int off = (r0 + 4 * q) ^ swc;
                float4 v0 = *reinterpret_cast<const float4 *>(b0p + off);
                float a0, a1, a2, a3;
                upk2(acc[2 * q][c],     a0, a1);
                upk2(acc[2 * q + 1][c], a2, a3);
                float4 v;
                v.x = a0 + v0.x;
                v.y = a1 + v0.y;
                v.z = a2 + v0.z;
                v.w = a3 + v0.w;
                if (ACT) {
                    v.x = tanhf(v.x); v.y = tanhf(v.y);
                    v.z = tanhf(v.z); v.w = tanhf(v.w);
                }
                *reinterpret_cast<float4 *>(dst + off) = v;
            }
        }
    }
    __syncthreads();
}

// ---------------------------------------------------------------------------
__global__ void __launch_bounds__(THREADS, 1)
node_kernel(const float *__restrict__ ts, const float *__restrict__ y0,
            const float *__restrict__ W0, const float *__restrict__ b0,
            const float *__restrict__ W1, const float *__restrict__ b1,
            const float *__restrict__ W2, const float *__restrict__ b2,
            const float *__restrict__ W3, const float *__restrict__ b3,
            float *__restrict__ out) {
    extern __shared__ float sm[];
    float *actA = sm;                       // [256][32] swizzled
    float *actB = actA + ACT_SIZE;
    float *red0 = actB + ACT_SIZE;          // [256][32]
    float *red1 = red0 + RED_SIZE;
    float *zbuf = red1 + RED_SIZE;          // [64][32] swizzled
    float *ybuf = zbuf + ZK_SIZE;
    float *kbuf = ybuf + ZK_SIZE;           // 6 * [64][32]

    const int tid = threadIdx.x;
    const int cta = blockIdx.x;

    // ingest y0 (row-major) -> ybuf (transposed swizzled); emit out[0]
    {
        const float *y0c = y0 + (size_t)cta * TM * DIM;
        float *o0 = out + (size_t)cta * TM * DIM;
        for (int i = tid; i < TM * DIM; i += THREADS) {
            const int r = i >> 6;        // batch row within tile
            const int d = i & 63;        // feature
            float v = __ldg(y0c + i);
            ybuf[d * TM + (r ^ SW(d))] = v;
            o0[i] = v;
        }
    }
    __syncthreads();

    for (int t = 1; t < NTT; ++t) {
        const float h = __ldg(ts + t) - __ldg(ts + t - 1);

        for (int s = 0; s < 6; ++s) {
            const float *zin;
            if (s == 0) {
                zin = ybuf;
            } else {
                // z = y + h * sum_{j<s} A[s][j] * k_j  (elementwise, any layout)
                float4 *zb = reinterpret_cast<float4 *>(zbuf);
                const float4 *yb = reinterpret_cast<const float4 *>(ybuf);
                for (int i = tid; i < ZK_SIZE / 4; i += THREADS) {
                    float4 v = yb[i];
                    for (int j = 0; j < s; j++) {
                        float c = h * c_A[s][j];
                        float4 kv = reinterpret_cast<const float4 *>(kbuf + j * ZK_SIZE)[i];
                        v.x += c * kv.x; v.y += c * kv.y;
                        v.z += c * kv.z; v.w += c * kv.w;
                    }
                    zb[i] = v;
                }
                zin = zbuf;
            }
            __syncthreads();

            layerT<DIM,   WIDTH, true >(zin,  actA, W0, b0, red0, red1);
            layerT<WIDTH, WIDTH, true >(actA, actB, W1, b1, red0, red1);
            layerT<WIDTH, WIDTH, true >(actB, actA, W2, b2, red0, red1);
            layerT<WIDTH, DIM,   false>(actA, kbuf + s * ZK_SIZE, W3, b3, red0, red1);
        }

        // y += h * sum_j B[j] * k_j  (elementwise)
        {
            float4 *yb = reinterpret_cast<float4 *>(ybuf);
            for (int i = tid; i < ZK_SIZE / 4; i += THREADS) {
                float4 v = yb[i];
#pragma unroll
                for (int j = 0; j < 6; j++) {
                    float c = h * c_B[j];
                    float4 kv = reinterpret_cast<const float4 *>(kbuf + j * ZK_SIZE)[i];
                    v.x += c * kv.x; v.y += c * kv.y;
                    v.z += c * kv.z; v.w += c * kv.w;
                }
                yb[i] = v;
            }
        }
        __syncthreads();

        // store out[t] (row-major, coalesced) from swizzled ybuf
        {
            float *outc = out + (size_t)t * (BATCH * DIM) + (size_t)cta * TM * DIM;
            for (int i = tid; i < TM * DIM; i += THREADS) {
                const int r = i >> 6;
                const int d = i & 63;
                outc[i] = ybuf[d * TM + (r ^ SW(d))];
            }
        }
        __syncthreads();
    }
}

// ---------------------------------------------------------------------------
extern "C" void kernel_launch(void *const *d_in, const int *in_sizes, int n_in,
                              void *d_out, int out_size) {
    const float *ts = (const float *)d_in[0];
    const float *y0 = (const float *)d_in[1];
    const float *W0 = (const float *)d_in[2];
    const float *b0 = (const float *)d_in[3];
    const float *W1 = (const float *)d_in[4];
    const float *b1 = (const float *)d_in[5];
    const float *W2 = (const float *)d_in[6];
    const float *b2 = (const float *)d_in[7];
    const float *W3 = (const float *)d_in[8];
    const float *b3 = (const float *)d_in[9];
    float *out = (float *)d_out;

    cudaFuncSetAttribute(node_kernel,
                         cudaFuncAttributeMaxDynamicSharedMemorySize, SMEM_BYTES);
    node_kernel<<<NCTA, THREADS, SMEM_BYTES>>>(ts, y0, W0, b0, W1, b1,
                                               W2, b2, W3, b3, out);
}

// round 6
// speedup vs baseline: 1.5968x; 1.5968x over previous
#include <cuda_runtime.h>
#include <cstdint>
#include <math.h>

// ---------------------------------------------------------------------------
// NeuralODE Tsit5 — persistent-CTA fp32 kernel, round 5.
// R4 dataflow (A broadcasts from SMEM, W via LDG, split-K 4) re-engineered
// for latency: 512 threads (4 warps/SMSP), 8x8 thread tile (64-reg acc),
// explicit W prefetch pipeline, swizzle math hoisted per 8-k group.
// ---------------------------------------------------------------------------

#define BATCH   4096
#define DIM     64
#define WIDTH   256
#define NTT     101
#define TM      32
#define NCTA    (BATCH / TM)      // 128
#define THREADS 512

// swizzle: element (idx, r) lives at slot r ^ SW(idx); SW multiple of 4
#define SW(idx) ((((idx) >> 3) & 7) << 2)

#define ACT_SIZE (WIDTH * TM)     // 8192 floats = 32KB
#define ZK_SIZE  (DIM * TM)       // 2048 floats = 8KB
#define RED_SIZE (WIDTH * TM)     // 8192 floats = 32KB

#define SMEM_FLOATS (2*ACT_SIZE + 2*RED_SIZE + ZK_SIZE + ZK_SIZE + 6*ZK_SIZE)
#define SMEM_BYTES  (SMEM_FLOATS * 4)   // 192KB

// Tsit5 tableau
__constant__ float c_A[6][5] = {
    {0.f, 0.f, 0.f, 0.f, 0.f},
    {0.161f, 0.f, 0.f, 0.f, 0.f},
    {-0.008480655492356989f, 0.335480655492357f, 0.f, 0.f, 0.f},
    {2.8971530571054935f, -6.359448489975075f, 4.3622954328695815f, 0.f, 0.f},
    {5.325864828439257f, -11.748883564062828f, 7.4955393428898365f, -0.09249506636175525f, 0.f},
    {5.86145544294642f, -12.92096931784711f, 8.159367898576159f, -0.071584973281401f, -0.028269050394068383f}
};
__constant__ float c_B[6] = {
    0.09646076681806523f, 0.01f, 0.4798896504144996f,
    1.379008574103742f, -3.290069515436081f, 2.324710524099774f
};

// ---- packed f32x2 helpers ----
__device__ __forceinline__ unsigned long long pk2(float lo, float hi) {
    unsigned long long r;
    asm("mov.b64 %0, {%1, %2};" : "=l"(r) : "f"(lo), "f"(hi));
    return r;
}
__device__ __forceinline__ void upk2(unsigned long long v, float &lo, float &hi) {
    asm("mov.b64 {%0, %1}, %2;" : "=f"(lo), "=f"(hi) : "l"(v));
}
__device__ __forceinline__ void ffma2(unsigned long long &d,
                                      unsigned long long a,
                                      unsigned long long b) {
    asm("fma.rn.f32x2 %0, %1, %2, %0;" : "+l"(d) : "l"(a), "l"(b));
}

// ---------------------------------------------------------------------------
// Dense layer:  Aout[c][r^SW(c)] = act( sum_k W[k][c]*Ain[k][r^SW(k)] + b[c] )
// Warp w: rg = w&3 -> rows rg*8..rg*8+7 (4 f32x2 pairs)
//         ks = w>>2 -> K-slice of 4
// Lane: CPL = N/32 columns at lane*CPL.
// Split-K: ks2->red0, ks3->red1 | ks1: acc+red0+red1 -> red0 | ks0: +red0,
// bias(in init), tanh -> Aout.
// ---------------------------------------------------------------------------
template <int K, int N, bool ACT>
__device__ __forceinline__ void layerT(const float *Ain, float *Aout,
                                       const float *__restrict__ Wg,
                                       const float *__restrict__ bg,
                                       float *red0, float *red1) {
    constexpr int CPL  = N / 32;       // 8 (N=256) or 2 (N=64)
    constexpr int KS   = K / 4;        // 64 or 16
    constexpr int NGRP = KS / 8;       // 8 or 2

    const int tid  = threadIdx.x;
    const int w    = tid >> 5;
    const int lane = tid & 31;
    const int rg   = w & 3;
    const int ks   = w >> 2;
    const int r0   = rg * 8;
    const int c0   = lane * CPL;

    unsigned long long acc[4][CPL];
    if (ks == 0) {
#pragma unroll
        for (int c = 0; c < CPL; c++) {
            float b = __ldg(bg + c0 + c);
            unsigned long long bb = pk2(b, b);
#pragma unroll
            for (int p = 0; p < 4; p++) acc[p][c] = bb;
        }
    } else {
#pragma unroll
        for (int p = 0; p < 4; p++)
#pragma unroll
            for (int c = 0; c < CPL; c++) acc[p][c] = 0ull;
    }

    // ---- W prefetch pipeline ----
    const float *Wk = Wg + (size_t)(ks * KS) * N + c0;
    float wn[CPL];
    if constexpr (CPL == 8) {
        float4 wa = __ldg(reinterpret_cast<const float4 *>(Wk));
        float4 wb = __ldg(reinterpret_cast<const float4 *>(Wk + 4));
        wn[0]=wa.x; wn[1]=wa.y; wn[2]=wa.z; wn[3]=wa.w;
        wn[4]=wb.x; wn[5]=wb.y; wn[6]=wb.z; wn[7]=wb.w;
    } else {
        float2 wa = __ldg(reinterpret_cast<const float2 *>(Wk));
        wn[0]=wa.x; wn[1]=wa.y;
    }
    Wk += N;

    for (int g = 0; g < NGRP; ++g) {
        const int kbase = ks * KS + g * 8;
        const int swk   = SW(kbase);       // constant over the 8-group
        const float *p0 = Ain + kbase * TM + ((r0 + 0) ^ swk);
        const float *p1 = Ain + kbase * TM + ((r0 + 2) ^ swk);
        const float *p2 = Ain + kbase * TM + ((r0 + 4) ^ swk);
        const float *p3 = Ain + kbase * TM + ((r0 + 6) ^ swk);

#pragma unroll
        for (int kk = 0; kk < 8; ++kk) {
            // A row-pair broadcasts (LDS.64, immediate offsets)
            unsigned long long ap0 = *reinterpret_cast<const unsigned long long *>(p0 + kk * TM);
            unsigned long long ap1 = *reinterpret_cast<const unsigned long long *>(p1 + kk * TM);
            unsigned long long ap2 = *reinterpret_cast<const unsigned long long *>(p2 + kk * TM);
            unsigned long long ap3 = *reinterpret_cast<const unsigned long long *>(p3 + kk * TM);

            // consume prefetched W, prefetch next
            float wc[CPL];
#pragma unroll
            for (int c = 0; c < CPL; c++) wc[c] = wn[c];

            if (kk < 7 || g + 1 < NGRP) {
                if constexpr (CPL == 8) {
                    float4 wa = __ldg(reinterpret_cast<const float4 *>(Wk));
                    float4 wb = __ldg(reinterpret_cast<const float4 *>(Wk + 4));
                    wn[0]=wa.x; wn[1]=wa.y; wn[2]=wa.z; wn[3]=wa.w;
                    wn[4]=wb.x; wn[5]=wb.y; wn[6]=wb.z; wn[7]=wb.w;
                } else {
                    float2 wa = __ldg(reinterpret_cast<const float2 *>(Wk));
                    wn[0]=wa.x; wn[1]=wa.y;
                }
            }
            Wk += N;

#pragma unroll
            for (int c = 0; c < CPL; c++) {
                unsigned long long wp = pk2(wc[c], wc[c]);
                ffma2(acc[0][c], ap0, wp);
                ffma2(acc[1][c], ap1, wp);
                ffma2(acc[2][c], ap2, wp);
                ffma2(acc[3][c], ap3, wp);
            }
        }
    }

    // ---- partial stores: ks2 -> red0, ks3 -> red1 ----
    if (ks >= 2) {
        float *dst = (ks == 2) ? red0 : red1;
#pragma unroll
        for (int c = 0; c < CPL; c++) {
            const int cc  = c0 + c;
            const int swc = SW(cc);
            float *base = dst + cc * TM;
#pragma unroll
            for (int q = 0; q < 2; q++) {
                float a0, a1, a2, a3;
                upk2(acc[2*q][c],   a0, a1);
                upk2(acc[2*q+1][c], a2, a3);
                float4 v; v.x=a0; v.y=a1; v.z=a2; v.w=a3;
                *reinterpret_cast<float4 *>(base + ((r0 + 4*q) ^ swc)) = v;
            }
        }
    }
    __syncthreads();

    // ---- ks1: acc + red0 + red1 -> red0 ----
    if (ks == 1) {
#pragma unroll
        for (int c = 0; c < CPL; c++) {
            const int cc  = c0 + c;
            const int swc = SW(cc);
            float *b0p = red0 + cc * TM;
            const float *b1p = red1 + cc * TM;
#pragma unroll
            for (int q = 0; q < 2; q++) {
                const int off = (r0 + 4*q) ^ swc;
                float4 v0 = *reinterpret_cast<const float4 *>(b0p + off);
                float4 v1 = *reinterpret_cast<const float4 *>(b1p + off);
                float a0, a1, a2, a3;
                upk2(acc[2*q][c],   a0, a1);
                upk2(acc[2*q+1][c], a2, a3);
                float4 v;
                v.x = a0 + v0.x + v1.x;
                v.y = a1 + v0.y + v1.y;
                v.z = a2 + v0.z + v1.z;
                v.w = a3 + v0.w + v1.w;
                *reinterpret_cast<float4 *>(b0p + off) = v;
            }
        }
    }
    __syncthreads();

    // ---- ks0: acc + red0, tanh, -> Aout ----
    if (ks == 0) {
#pragma unroll
        for (int c = 0; c < CPL; c++) {
            const int cc  = c0 + c;
            const int swc = SW(cc);
            const float *b0p = red0 + cc * TM;
            float *dst = Aout + cc * TM;
#pragma unroll
            for (int q = 0; q < 2; q++) {
                const int off = (r0 + 4*q) ^ swc;
                float4 v0 = *reinterpret_cast<const float4 *>(b0p + off);
                float a0, a1, a2, a3;
                upk2(acc[2*q][c],   a0, a1);
                upk2(acc[2*q+1][c], a2, a3);
                float4 v;
                v.x = a0 + v0.x;
                v.y = a1 + v0.y;
                v.z = a2 + v0.z;
                v.w = a3 + v0.w;
                if (ACT) {
                    v.x = tanhf(v.x); v.y = tanhf(v.y);
                    v.z = tanhf(v.z); v.w = tanhf(v.w);
                }
                *reinterpret_cast<float4 *>(dst + off) = v;
            }
        }
    }
    __syncthreads();
}

// ---------------------------------------------------------------------------
__global__ void __launch_bounds__(THREADS, 1)
node_kernel(const float *__restrict__ ts, const float *__restrict__ y0,
            const float *__restrict__ W0, const float *__restrict__ b0,
            const float *__restrict__ W1, const float *__restrict__ b1,
            const float *__restrict__ W2, const float *__restrict__ b2,
            const float *__restrict__ W3, const float *__restrict__ b3,
            float *__restrict__ out) {
    extern __shared__ float sm[];
    float *actA = sm;                       // [256][32] swizzled
    float *actB = actA + ACT_SIZE;
    float *red0 = actB + ACT_SIZE;
    float *red1 = red0 + RED_SIZE;
    float *zbuf = red1 + RED_SIZE;          // [64][32] swizzled
    float *ybuf = zbuf + ZK_SIZE;
    float *kbuf = ybuf + ZK_SIZE;           // 6 * [64][32]

    const int tid = threadIdx.x;
    const int cta = blockIdx.x;

    // ingest y0 (row-major) -> ybuf (transposed swizzled); emit out[0]
    {
        const float *y0c = y0 + (size_t)cta * TM * DIM;
        float *o0 = out + (size_t)cta * TM * DIM;
        for (int i = tid; i < TM * DIM; i += THREADS) {
            const int r = i >> 6;
            const int d = i & 63;
            float v = __ldg(y0c + i);
            ybuf[d * TM + (r ^ SW(d))] = v;
            o0[i] = v;
        }
    }
    __syncthreads();

    for (int t = 1; t < NTT; ++t) {
        const float h = __ldg(ts + t) - __ldg(ts + t - 1);

        for (int s = 0; s < 6; ++s) {
            const float *zin;
            if (s == 0) {
                zin = ybuf;
            } else {
                // z = y + h * sum_{j<s} A[s][j]*k_j (elementwise, same layout)
                float4 *zb = reinterpret_cast<float4 *>(zbuf);
                const float4 *yb = reinterpret_cast<const float4 *>(ybuf);
                for (int i = tid; i < ZK_SIZE / 4; i += THREADS) {
                    float4 v = yb[i];
                    for (int j = 0; j < s; j++) {
                        float c = h * c_A[s][j];
                        float4 kv = reinterpret_cast<const float4 *>(kbuf + j * ZK_SIZE)[i];
                        v.x += c * kv.x; v.y += c * kv.y;
                        v.z += c * kv.z; v.w += c * kv.w;
                    }
                    zb[i] = v;
                }
                zin = zbuf;
            }
            __syncthreads();

            layerT<DIM,   WIDTH, true >(zin,  actA, W0, b0, red0, red1);
            layerT<WIDTH, WIDTH, true >(actA, actB, W1, b1, red0, red1);
            layerT<WIDTH, WIDTH, true >(actB, actA, W2, b2, red0, red1);
            layerT<WIDTH, DIM,   false>(actA, kbuf + s * ZK_SIZE, W3, b3, red0, red1);
        }

        // y += h * sum_j B[j]*k_j (elementwise)
        {
            float4 *yb = reinterpret_cast<float4 *>(ybuf);
            for (int i = tid; i < ZK_SIZE / 4; i += THREADS) {
                float4 v = yb[i];
#pragma unroll
                for (int j = 0; j < 6; j++) {
                    float c = h * c_B[j];
                    float4 kv = reinterpret_cast<const float4 *>(kbuf + j * ZK_SIZE)[i];
                    v.x += c * kv.x; v.y += c * kv.y;
                    v.z += c * kv.z; v.w += c * kv.w;
                }
                yb[i] = v;
            }
        }
        __syncthreads();

        // store out[t] (row-major, coalesced) from swizzled ybuf
        {
            float *outc = out + (size_t)t * (BATCH * DIM) + (size_t)cta * TM * DIM;
            for (int i = tid; i < TM * DIM; i += THREADS) {
                const int r = i >> 6;
                const int d = i & 63;
                outc[i] = ybuf[d * TM + (r ^ SW(d))];
            }
        }
        __syncthreads();
    }
}

// ---------------------------------------------------------------------------
extern "C" void kernel_launch(void *const *d_in, const int *in_sizes, int n_in,
                              void *d_out, int out_size) {
    const float *ts = (const float *)d_in[0];
    const float *y0 = (const float *)d_in[1];
    const float *W0 = (const float *)d_in[2];
    const float *b0 = (const float *)d_in[3];
    const float *W1 = (const float *)d_in[4];
    const float *b1 = (const float *)d_in[5];
    const float *W2 = (const float *)d_in[6];
    const float *b2 = (const float *)d_in[7];
    const float *W3 = (const float *)d_in[8];
    const float *b3 = (const float *)d_in[9];
    float *out = (float *)d_out;

    cudaFuncSetAttribute(node_kernel,
                         cudaFuncAttributeMaxDynamicSharedMemorySize, SMEM_BYTES);
    node_kernel<<<NCTA, THREADS, SMEM_BYTES>>>(ts, y0, W0, b0, W1, b1,
                                               W2, b2, W3, b3, out);
}